// round 1
// baseline (speedup 1.0000x reference)
#include <cuda_runtime.h>

// ---------------- Problem constants (fixed by setup_inputs) ----------------
namespace {
constexpr int B = 8;
constexpr int S = 2048;
constexpr int D = 2048;
constexpr int M = 4088;          // merged length
constexpr int TOK_IN  = 128011;
constexpr int TOK_OUT = 128012;
constexpr int TOK_PAD = 128001;
constexpr int IGNORE_ID = -100;
constexpr int MAX_PH = 16384;    // safety bound on placeholders
}

// ---------------- Device scratch (no dynamic allocation allowed) -----------
__device__ int g_src[B * M];        // per output column: encoded source
__device__ int g_in_base[B];        // exclusive prefix of per-row IN counts
__device__ int g_out_base[B];
__device__ int g_ph_in_b[MAX_PH];   // per global IN placeholder: batch row
__device__ int g_ph_in_end[MAX_PH]; // per global IN placeholder: last merged col
__device__ int g_ph_out_b[MAX_PH];
__device__ int g_ph_out_end[MAX_PH];

// src encoding: -1 = empty (zero embedding); else (kind<<28)|idx
//   kind 0: text, idx = s  (source row = b*S + s of inputs_embeds)
//   kind 1: audio_in, idx = row into audio_in_embed
//   kind 2: audio_out, idx = row into audio_out_embed

// ---------------- Block-wide exclusive scan (256 threads) ------------------
__device__ __forceinline__ int blk_excl_scan(int v, int& total, int* s_warp) {
    const unsigned FULL = 0xFFFFFFFFu;
    int lane = threadIdx.x & 31, wid = threadIdx.x >> 5;
    int x = v;
#pragma unroll
    for (int o = 1; o < 32; o <<= 1) {
        int y = __shfl_up_sync(FULL, x, o);
        if (lane >= o) x += y;
    }
    // x = inclusive scan within warp
    if (lane == 31) s_warp[wid] = x;
    __syncthreads();
    if (wid == 0 && lane < 8) {
        int t = s_warp[lane];
        int xt = t;
#pragma unroll
        for (int o = 1; o < 8; o <<= 1) {
            int y = __shfl_up_sync(0xFFu, xt, o);
            if (lane >= o) xt += y;
        }
        s_warp[lane] = xt - t;        // exclusive warp prefix
        if (lane == 7) s_warp[8] = xt; // block total
    }
    __syncthreads();
    total = s_warp[8];
    int res = s_warp[wid] + x - v;     // exclusive prefix for this thread
    __syncthreads();                   // allow s_warp reuse by caller
    return res;
}

// ---------------- Kernel 0: per-row placeholder counts ---------------------
__global__ void k_count(const int* __restrict__ ids) {
    // 256 threads = 8 warps, one warp per batch row
    int b = threadIdx.x >> 5;
    int lane = threadIdx.x & 31;
    int cin = 0, cout = 0;
    for (int s = lane; s < S; s += 32) {
        int v = ids[b * S + s];
        cin  += (v == TOK_IN);
        cout += (v == TOK_OUT);
    }
#pragma unroll
    for (int o = 16; o; o >>= 1) {
        cin  += __shfl_down_sync(0xFFFFFFFFu, cin, o);
        cout += __shfl_down_sync(0xFFFFFFFFu, cout, o);
    }
    __shared__ int sin[B], sout[B];
    if (lane == 0) { sin[b] = cin; sout[b] = cout; }
    __syncthreads();
    if (threadIdx.x == 0) {
        int ai = 0, ao = 0;
        for (int r = 0; r < B; r++) {
            g_in_base[r] = ai;  g_out_base[r] = ao;
            ai += sin[r];       ao += sout[r];
        }
    }
}

// ---------------- Kernel 1: per-row merge layout + text scatter -------------
__global__ void k_row(const int* __restrict__ ids,
                      const int* __restrict__ amask,
                      const int* __restrict__ labels,
                      const int* __restrict__ in_starts,
                      const int* __restrict__ out_starts,
                      int n_in, int n_out, int tot_in, int tot_out,
                      float* __restrict__ out) {
    __shared__ int s_ids[S];
    __shared__ int s_warp[9];
    const int b = blockIdx.x, t = threadIdx.x;

    // small-output section bases (all float32, concatenated after embedding)
    float* o_attn = out + (long long)B * M * D;
    float* o_lab  = o_attn + (long long)B * M;
    float* o_id   = o_lab  + 2LL * B * M;  // skip position_ids slot (o_lab + B*M is pos)
    float* o_ifil = o_id   + (long long)B * M;
    float* o_idis = o_ifil + (long long)B * M;
    float* o_ofil = o_idis + (long long)B * M;

    // load this row's ids into shared
    for (int s = t; s < S; s += 256) s_ids[s] = ids[b * S + s];

    // defaults for all M merged columns of this row
    for (int m = t; m < M; m += 256) {
        int idx = b * M + m;
        g_src[idx]  = -1;
        o_attn[idx] = 0.0f;
        o_lab[idx]  = (float)IGNORE_ID;
        o_id[idx]   = (float)TOK_PAD;
        o_ifil[idx] = 0.0f;
        o_idis[idx] = 0.0f;
        o_ofil[idx] = 0.0f;
    }
    __syncthreads();

    // 8 sequential items per thread
    const int base = t * 8;
    int vin[8], vout[8];
    int lin = 0, lout = 0;
#pragma unroll
    for (int j = 0; j < 8; j++) {
        int v = s_ids[base + j];
        vin[j]  = (v == TOK_IN);
        vout[j] = (v == TOK_OUT);
        lin += vin[j]; lout += vout[j];
    }
    // joint exclusive scan of (in_count, out_count) packed
    int dummy;
    int ex = blk_excl_scan((lin << 16) | lout, dummy, s_warp);
    const int ex_in = ex >> 16, ex_out = ex & 0xFFFF;

    // token-per-position with placeholder expansion lengths
    const int ib = g_in_base[b], ob = g_out_base[b];
    int tpn[8];
    {
        int oin = ex_in, oout = ex_out;
#pragma unroll
        for (int j = 0; j < 8; j++) {
            int v = 1;
            if (vin[j]) {
                int p  = ib + oin; oin++;
                int st = in_starts[p];
                int en = (p + 1 < n_in) ? in_starts[p + 1] : tot_in;
                v = en - st;
            } else if (vout[j]) {
                int p  = ob + oout; oout++;
                int st = out_starts[p];
                int en = (p + 1 < n_out) ? out_starts[p + 1] : tot_out;
                v = en - st;
            }
            tpn[j] = v;
        }
    }
    int tsum = 0;
#pragma unroll
    for (int j = 0; j < 8; j++) tsum += tpn[j];
    int total;
    int ex2 = blk_excl_scan(tsum, total, s_warp);
    const int shift = M - total;   // left-pad shift (0 when row fills M exactly)

    // scatter: text columns + placeholder records
    {
        int run = ex2, oin = ex_in, oout = ex_out;
#pragma unroll
        for (int j = 0; j < 8; j++) {
            run += tpn[j];
            const int np = run - 1 + shift;   // last merged column for this token
            const int s  = base + j;
            if (vin[j]) {
                int p = ib + oin; oin++;
                g_ph_in_b[p] = b;  g_ph_in_end[p] = np;
            } else if (vout[j]) {
                int p = ob + oout; oout++;
                g_ph_out_b[p] = b; g_ph_out_end[p] = np;
            } else {
                int idx = b * M + np;
                g_src[idx]  = s;                         // kind 0 = text
                o_attn[idx] = (float)amask[b * S + s];
                o_lab[idx]  = (float)labels[b * S + s];
                o_id[idx]   = (float)s_ids[s];
            }
        }
    }
}

// ---------------- Kernel 2: audio column scatter ---------------------------
__global__ void k_audio(const int* __restrict__ in_starts,
                        const int* __restrict__ out_starts,
                        int n_in, int n_out, int tot_in, int tot_out,
                        float* __restrict__ out) {
    float* o_attn = out + (long long)B * M * D;
    float* o_lab  = o_attn + (long long)B * M;
    float* o_id   = o_lab  + 2LL * B * M;
    float* o_ifil = o_id   + (long long)B * M;
    float* o_idis = o_ifil + (long long)B * M;
    float* o_ofil = o_idis + (long long)B * M;

    const int p = blockIdx.x;
    int b, endc, st, len, kind, tok;
    if (p < n_in) {
        b = g_ph_in_b[p]; endc = g_ph_in_end[p];
        st = in_starts[p];
        len = ((p + 1 < n_in) ? in_starts[p + 1] : tot_in) - st;
        kind = 1; tok = TOK_IN;
    } else {
        int q = p - n_in;
        b = g_ph_out_b[q]; endc = g_ph_out_end[q];
        st = out_starts[q];
        len = ((q + 1 < n_out) ? out_starts[q + 1] : tot_out) - st;
        kind = 2; tok = TOK_OUT;
    }
    const int cstart = endc - len + 1;
    for (int j = threadIdx.x; j < len; j += blockDim.x) {
        int idx = b * M + cstart + j;
        g_src[idx]  = (kind << 28) | (st + j);
        o_attn[idx] = 1.0f;
        o_lab[idx]  = (float)IGNORE_ID;
        o_id[idx]   = (float)tok;
        if (kind == 1) { o_ifil[idx] = 1.0f; o_idis[idx] = 1.0f; }
        else           { o_ofil[idx] = 1.0f; }
    }
}

// ---------------- Kernel 3: position_ids (per-row cumsum of attention) -----
__global__ void k_pos(float* __restrict__ out) {
    __shared__ int s_warp[9];
    const int b = blockIdx.x, t = threadIdx.x;
    float* o_attn = out + (long long)B * M * D;
    float* o_pos  = o_attn + 2LL * B * M;

    int a[16];
    int sum = 0;
#pragma unroll
    for (int j = 0; j < 16; j++) {
        int m = t * 16 + j;
        a[j] = (m < M) ? (int)o_attn[b * M + m] : 0;
        sum += a[j];
    }
    int total;
    int ex = blk_excl_scan(sum, total, s_warp);
    int run = ex;
#pragma unroll
    for (int j = 0; j < 16; j++) {
        run += a[j];
        int m = t * 16 + j;
        if (m < M) {
            int pos = (a[j] == 0) ? 1 : (run - 1);
            o_pos[b * M + m] = (float)pos;
        }
    }
}

// ---------------- Kernel 4: the bandwidth kernel (row gather copy) ---------
__global__ void __launch_bounds__(256) k_copy(const float* __restrict__ in_emb,
                                              const float* __restrict__ out_emb,
                                              const float* __restrict__ text_emb,
                                              float* __restrict__ out) {
    const int row = blockIdx.x;           // b*M + m
    const int src = g_src[row];
    float4* dst = reinterpret_cast<float4*>(out) + (long long)row * (D / 4);
    if (src < 0) {
        const float4 z = make_float4(0.f, 0.f, 0.f, 0.f);
#pragma unroll
        for (int i = threadIdx.x; i < D / 4; i += 256) dst[i] = z;
        return;
    }
    const int kind = src >> 28;
    const int idx  = src & 0x0FFFFFFF;
    const float* sp;
    if (kind == 0) {
        const int b = row / M;
        sp = text_emb + ((long long)b * S + idx) * D;
    } else if (kind == 1) {
        sp = in_emb + (long long)idx * D;
    } else {
        sp = out_emb + (long long)idx * D;
    }
    const float4* s4 = reinterpret_cast<const float4*>(sp);
#pragma unroll
    for (int i = threadIdx.x; i < D / 4; i += 256) dst[i] = s4[i];
}

// ---------------- Launch -----------------------------------------------------
extern "C" void kernel_launch(void* const* d_in, const int* in_sizes, int n_in_args,
                              void* d_out, int out_size) {
    const float* audio_in_embed  = (const float*)d_in[0];
    const float* audio_out_embed = (const float*)d_in[1];
    const float* inputs_embeds   = (const float*)d_in[2];
    const int*   in_starts       = (const int*)d_in[3];
    const int*   out_starts      = (const int*)d_in[4];
    const int*   input_ids       = (const int*)d_in[5];
    const int*   attention_mask  = (const int*)d_in[6];
    const int*   label_ids       = (const int*)d_in[7];
    (void)n_in_args; (void)out_size;

    const int n_in  = in_sizes[3];
    const int n_out = in_sizes[4];
    const int tot_in  = in_sizes[0] / D;
    const int tot_out = in_sizes[1] / D;

    float* out = (float*)d_out;

    k_count<<<1, 256>>>(input_ids);
    k_row<<<B, 256>>>(input_ids, attention_mask, label_ids,
                      in_starts, out_starts, n_in, n_out, tot_in, tot_out, out);
    k_audio<<<n_in + n_out, 256>>>(in_starts, out_starts,
                                   n_in, n_out, tot_in, tot_out, out);
    k_pos<<<B, 256>>>(out);
    k_copy<<<B * M, 256>>>(audio_in_embed, audio_out_embed, inputs_embeds, out);
}